// round 14
// baseline (speedup 1.0000x reference)
#include <cuda_runtime.h>
#include <cstdint>

#define B 8
#define S 2048
#define DM 1024
#define DK 64
#define ROWS (B * S)

// ---------------- scratch (device globals; no allocation allowed) ----------
__device__ float g_Xt[(size_t)ROWS * DM];   // X, tf32-rounded (64 MB)
__device__ float g_Q[ROWS * DK];            // tf32-rounded
__device__ float g_K[ROWS * DK];            // tf32-rounded
__device__ float g_V[ROWS * DM];            // tf32-rounded (64 MB)
__device__ float g_L[ROWS];
__device__ float g_P[(size_t)ROWS * S];     // scores, then tf32-rounded probs
__device__ float g_WvT[DM * DM];            // Wv^T, K-major, tf32-rounded
__device__ float g_WqkT[128 * DM];          // [Wq|Wk]^T, K-major, tf32-rounded
__device__ float g_bqk[128];

// ======================= helpers ==========================================
__device__ __forceinline__ uint32_t f2tf32(float f) {
    uint32_t o;
    asm("cvt.rna.tf32.f32 %0, %1;" : "=r"(o) : "f"(f));
    return o;
}
__device__ __forceinline__ float rtf(float f) { return __uint_as_float(f2tf32(f)); }

__device__ __forceinline__ uint32_t smem_u32(const void* p) {
    uint32_t a;
    asm("{ .reg .u64 t; cvta.to.shared.u64 t, %1; cvt.u32.u64 %0, t; }"
        : "=r"(a) : "l"(p));
    return a;
}
__device__ __forceinline__ void cpa16(uint32_t dst, const float* src) {
    asm volatile("cp.async.cg.shared.global [%0], [%1], 16;"
                 :: "r"(dst), "l"(src));
}
#define CP_COMMIT() asm volatile("cp.async.commit_group;" ::: "memory")
#define CP_WAIT1()  asm volatile("cp.async.wait_group 1;" ::: "memory")

// XOR-swizzled word index inside a 128x16-word tile (conflict-free frags)
__device__ __forceinline__ int swz(int m, int k) {
    return (m << 4) + ((((k >> 2) ^ ((m >> 1) & 3)) << 2)) + (k & 3);
}
// V-tile swizzle: 16 rows x 128 words, flip word-index bits 3-4 by (k&3)
__device__ __forceinline__ int vswz(int k, int d) {
    return (k << 7) + (d ^ ((k & 3) << 3));
}

__device__ __forceinline__ void ldsm4(uint32_t r[4], uint32_t addr) {
    asm volatile("ldmatrix.sync.aligned.m8n8.x4.shared.b16 {%0,%1,%2,%3}, [%4];"
        : "=r"(r[0]), "=r"(r[1]), "=r"(r[2]), "=r"(r[3]) : "r"(addr));
}
__device__ __forceinline__ void ldsm2(uint32_t r[2], uint32_t addr) {
    asm volatile("ldmatrix.sync.aligned.m8n8.x2.shared.b16 {%0,%1}, [%2];"
        : "=r"(r[0]), "=r"(r[1]) : "r"(addr));
}

__device__ __forceinline__ void mma_tf32(float c[4], const uint32_t a[4],
                                         const uint32_t b[2]) {
    asm volatile(
        "mma.sync.aligned.m16n8k8.row.col.f32.tf32.tf32.f32 "
        "{%0,%1,%2,%3}, {%4,%5,%6,%7}, {%8,%9}, {%0,%1,%2,%3};"
        : "+f"(c[0]), "+f"(c[1]), "+f"(c[2]), "+f"(c[3])
        : "r"(a[0]), "r"(a[1]), "r"(a[2]), "r"(a[3]), "r"(b[0]), "r"(b[1]));
}

// ===========================================================================
// Prep kernels
// ===========================================================================
__global__ __launch_bounds__(256) void round_x_kernel(const float* __restrict__ X)
{
    size_t i = (size_t)blockIdx.x * 256 + threadIdx.x;
    float4 v = reinterpret_cast<const float4*>(X)[i];
    float4 o = {rtf(v.x), rtf(v.y), rtf(v.z), rtf(v.w)};
    reinterpret_cast<float4*>(g_Xt)[i] = o;
}

__global__ __launch_bounds__(256) void transpose_wv_kernel(const float* __restrict__ Wv)
{
    __shared__ float t[32][33];
    const int k0 = blockIdx.x * 32, n0 = blockIdx.y * 32;
    const int tx = threadIdx.x, ty = threadIdx.y;
#pragma unroll
    for (int i = 0; i < 32; i += 8)
        t[ty + i][tx] = Wv[(k0 + ty + i) * DM + n0 + tx];
    __syncthreads();
#pragma unroll
    for (int i = 0; i < 32; i += 8)
        g_WvT[(n0 + ty + i) * DM + k0 + tx] = rtf(t[tx][ty + i]);
}

__global__ __launch_bounds__(256) void prep_qk_kernel(
    const float* __restrict__ Wq, const float* __restrict__ bq,
    const float* __restrict__ Wk, const float* __restrict__ bk)
{
    __shared__ float t[32][33];
    const int k0 = blockIdx.x * 32, n0 = blockIdx.y * 32;
    const int tx = threadIdx.x, ty = threadIdx.y;
    const int n = n0 + tx;
#pragma unroll
    for (int i = 0; i < 32; i += 8) {
        int k = k0 + ty + i;
        t[ty + i][tx] = (n < 64) ? Wq[k * DK + n] : Wk[k * DK + (n - 64)];
    }
    __syncthreads();
#pragma unroll
    for (int i = 0; i < 32; i += 8)
        g_WqkT[(n0 + ty + i) * DM + k0 + tx] = rtf(t[tx][ty + i]);
    if (blockIdx.x == 0 && blockIdx.y == 0) {
        int id = ty * 32 + tx;
        if (id < 128) g_bqk[id] = (id < 64) ? bq[id] : bk[id - 64];
    }
}

// ===========================================================================
// Merged projections: grid (128, 9).  blockIdx.y < 8 -> V tile (Bt=g_WvT,
// +bv); blockIdx.y == 8 -> Q|K tile (Bt=g_WqkT, +g_bqk, nc=0).
// 3-stage cp.async ring, ldmatrix fragment loads.
// BM=128 BN=128 BK=16, 8 warps 2x4, warp 64x32.
// ===========================================================================
__global__ __launch_bounds__(256, 2) void gemm_tc_kernel(const float* __restrict__ bv)
{
    __shared__ uint32_t sA[3][2048];   // 24 KB
    __shared__ uint32_t sB[3][2048];   // 24 KB

    const int mode = (blockIdx.y == 8);
    const float* A  = g_Xt;
    const float* Bt = mode ? g_WqkT : g_WvT;

    const int r0   = blockIdx.x * 128;
    const int nc   = mode ? 0 : blockIdx.y * 128;
    const int tid  = threadIdx.x;
    const int wid  = tid >> 5;
    const int lane = tid & 31;
    const int wm   = (wid >> 2) * 64;
    const int wn   = (wid & 3) * 32;
    const int lr   = lane >> 2;
    const int lc   = lane & 3;

    const int cm = tid >> 2, cc = tid & 3;
    uint32_t dA[2], dB[2];
    const float *pA[2], *pB[2];
#pragma unroll
    for (int it = 0; it < 2; it++) {
        int m = cm + it * 64;
        int w = (m << 4) + (((cc ^ ((m >> 1) & 3))) << 2);
        dA[it] = smem_u32(&sA[0][0]) + 4 * w;
        dB[it] = smem_u32(&sB[0][0]) + 4 * w;
        pA[it] = A  + (size_t)(r0 + m) * DM + cc * 4;
        pB[it] = Bt + (size_t)(nc + m) * DM + cc * 4;
    }

    // ldmatrix addresses (stage 0, ks 0)
    const int lane7 = lane & 7;
    uint32_t adA[4], adB[4];
    {
        const int akq = (lane >> 4) & 1;
        const int ar0 = wm + lane7 + ((lane >> 3) & 1) * 8;
#pragma unroll
        for (int mi = 0; mi < 4; mi++) {
            int arow = ar0 + mi * 16;
            int h = (arow >> 1) & 3;
            adA[mi] = smem_u32(&sA[0][0]) + 4 * ((arow << 4) + ((akq ^ h) << 2));
        }
        const int bkq = (lane >> 3) & 1;
#pragma unroll
        for (int ni = 0; ni < 4; ni++) {
            int brow = wn + ni * 8 + lane7;
            int h = (brow >> 1) & 3;
            adB[ni] = smem_u32(&sB[0][0]) + 4 * ((brow << 4) + ((bkq ^ h) << 2));
        }
    }

    float acc[4][4][4];
#pragma unroll
    for (int mi = 0; mi < 4; mi++)
#pragma unroll
        for (int ni = 0; ni < 4; ni++)
#pragma unroll
            for (int r = 0; r < 4; r++) acc[mi][ni][r] = 0.f;

    const int NT = DM / 16;
#pragma unroll
    for (int t = 0; t < 2; t++) {
        const uint32_t off = t * 8192u;
        const int kc = t * 16;
#pragma unroll
        for (int it = 0; it < 2; it++) {
            cpa16(dA[it] + off, pA[it] + kc);
            cpa16(dB[it] + off, pB[it] + kc);
        }
        CP_COMMIT();
    }

    int cur = 0;
    for (int kt = 0; kt < NT; kt++) {
        CP_WAIT1();
        __syncthreads();
        {
            int nx = cur + 2; if (nx >= 3) nx -= 3;
            if (kt + 2 < NT) {
                const int kc = (kt + 2) * 16;
                const uint32_t off = nx * 8192u;
#pragma unroll
                for (int it = 0; it < 2; it++) {
                    cpa16(dA[it] + off, pA[it] + kc);
                    cpa16(dB[it] + off, pB[it] + kc);
                }
            }
            CP_COMMIT();
        }
        const uint32_t so = cur * 8192u;
#pragma unroll
        for (int ks = 0; ks < 2; ks++) {
            const uint32_t kx = ks << 5;
            uint32_t a[4][4], b[4][2];
#pragma unroll
            for (int mi = 0; mi < 4; mi++) ldsm4(a[mi], (adA[mi] ^ kx) + so);
#pragma unroll
            for (int ni = 0; ni < 4; ni++) ldsm2(b[ni], (adB[ni] ^ kx) + so);
#pragma unroll
            for (int mi = 0; mi < 4; mi++)
#pragma unroll
                for (int ni = 0; ni < 4; ni++)
                    mma_tf32(acc[mi][ni], a[mi], b[ni]);
        }
        cur++; if (cur >= 3) cur = 0;
    }

#pragma unroll
    for (int mi = 0; mi < 4; mi++) {
#pragma unroll
        for (int ni = 0; ni < 4; ni++) {
#pragma unroll
            for (int h = 0; h < 2; h++) {
                int row = r0 + wm + mi * 16 + lr + h * 8;
                int col = wn + ni * 8 + 2 * lc;
                float v0 = acc[mi][ni][h * 2 + 0];
                float v1 = acc[mi][ni][h * 2 + 1];
                if (!mode) {
                    float2 o = {rtf(v0 + bv[nc + col]), rtf(v1 + bv[nc + col + 1])};
                    *reinterpret_cast<float2*>(&g_V[(size_t)row * DM + nc + col]) = o;
                } else {
                    float2 o = {rtf(v0 + g_bqk[col]), rtf(v1 + g_bqk[col + 1])};
                    if (col < 64)
                        *reinterpret_cast<float2*>(&g_Q[(size_t)row * DK + col]) = o;
                    else
                        *reinterpret_cast<float2*>(&g_K[(size_t)row * DK + (col - 64)]) = o;
                }
            }
        }
    }
}

// ===========================================================================
// score_kernel: one 128x128 causal tile of S = Q K^T / 8 per CTA (raw fp32,
// masked = -1e30).  3-stage ring + ldmatrix, NT = 4.
// ===========================================================================
__global__ __launch_bounds__(256, 2) void score_kernel()
{
    __shared__ uint32_t sA[3][2048];
    __shared__ uint32_t sB[3][2048];

    int i = blockIdx.x;
    int qt = (int)((sqrtf(8.f * (float)i + 1.f) - 1.f) * 0.5f);
    while ((qt + 1) * (qt + 2) / 2 <= i) qt++;
    while (qt * (qt + 1) / 2 > i) qt--;
    const int kt = i - qt * (qt + 1) / 2;

    const int b     = blockIdx.y;
    const int qbase = b * S + qt * 128;
    const int kbase = b * S + kt * 128;

    const int tid  = threadIdx.x;
    const int wid  = tid >> 5;
    const int lane = tid & 31;
    const int wm   = (wid >> 2) * 64;
    const int wn   = (wid & 3) * 32;
    const int lr   = lane >> 2;
    const int lc   = lane & 3;

    const int cm = tid >> 2, cc = tid & 3;
    uint32_t dA[2], dB[2];
    const float *pA[2], *pB[2];
#pragma unroll
    for (int it = 0; it < 2; it++) {
        int m = cm + it * 64;
        int w = (m << 4) + (((cc ^ ((m >> 1) & 3))) << 2);
        dA[it] = smem_u32(&sA[0][0]) + 4 * w;
        dB[it] = smem_u32(&sB[0][0]) + 4 * w;
        pA[it] = g_Q + (size_t)(qbase + m) * DK + cc * 4;
        pB[it] = g_K + (size_t)(kbase + m) * DK + cc * 4;
    }

    const int lane7 = lane & 7;
    uint32_t adA[4], adB[4];
    {
        const int akq = (lane >> 4) & 1;
        const int ar0 = wm + lane7 + ((lane >> 3) & 1) * 8;
#pragma unroll
        for (int mi = 0; mi < 4; mi++) {
            int arow = ar0 + mi * 16;
            int h = (arow >> 1) & 3;
            adA[mi] = smem_u32(&sA[0][0]) + 4 * ((arow << 4) + ((akq ^ h) << 2));
        }
        const int bkq = (lane >> 3) & 1;
#pragma unroll
        for (int ni = 0; ni < 4; ni++) {
            int brow = wn + ni * 8 + lane7;
            int h = (brow >> 1) & 3;
            adB[ni] = smem_u32(&sB[0][0]) + 4 * ((brow << 4) + ((bkq ^ h) << 2));
        }
    }

    float acc[4][4][4];
#pragma unroll
    for (int mi = 0; mi < 4; mi++)
#pragma unroll
        for (int ni = 0; ni < 4; ni++)
#pragma unroll
            for (int r = 0; r < 4; r++) acc[mi][ni][r] = 0.f;

    const int NT = DK / 16;   // 4
#pragma unroll
    for (int t = 0; t < 2; t++) {
        const uint32_t off = t * 8192u;
        const int kc = t * 16;
#pragma unroll
        for (int it = 0; it < 2; it++) {
            cpa16(dA[it] + off, pA[it] + kc);
            cpa16(dB[it] + off, pB[it] + kc);
        }
        CP_COMMIT();
    }

    int cur = 0;
    for (int ktile = 0; ktile < NT; ktile++) {
        CP_WAIT1();
        __syncthreads();
        {
            int nx = cur + 2; if (nx >= 3) nx -= 3;
            if (ktile + 2 < NT) {
                const int kc = (ktile + 2) * 16;
                const uint32_t off = nx * 8192u;
#pragma unroll
                for (int it = 0; it < 2; it++) {
                    cpa16(dA[it] + off, pA[it] + kc);
                    cpa16(dB[it] + off, pB[it] + kc);
                }
            }
            CP_COMMIT();
        }
        const uint32_t so = cur * 8192u;
#pragma unroll
        for (int ks = 0; ks < 2; ks++) {
            const uint32_t kx = ks << 5;
            uint32_t a[4][4], b2[4][2];
#pragma unroll
            for (int mi = 0; mi < 4; mi++) ldsm4(a[mi], (adA[mi] ^ kx) + so);
#pragma unroll
            for (int ni = 0; ni < 4; ni++) ldsm2(b2[ni], (adB[ni] ^ kx) + so);
#pragma unroll
            for (int mi = 0; mi < 4; mi++)
#pragma unroll
                for (int ni = 0; ni < 4; ni++)
                    mma_tf32(acc[mi][ni], a[mi], b2[ni]);
        }
        cur++; if (cur >= 3) cur = 0;
    }

#pragma unroll
    for (int mi = 0; mi < 4; mi++) {
#pragma unroll
        for (int ni = 0; ni < 4; ni++) {
#pragma unroll
            for (int h = 0; h < 2; h++) {
                int qrow = qt * 128 + wm + mi * 16 + lr + h * 8;
                int kcol = kt * 128 + wn + ni * 8 + 2 * lc;
                float v0 = acc[mi][ni][h * 2 + 0] * 0.125f;
                float v1 = acc[mi][ni][h * 2 + 1] * 0.125f;
                if (kcol > qrow)     v0 = -1e30f;
                if (kcol + 1 > qrow) v1 = -1e30f;
                float2 o = {v0, v1};
                *reinterpret_cast<float2*>(
                    &g_P[(size_t)(b * S + qrow) * S + kcol]) = o;
            }
        }
    }
}

// ===========================================================================
// rowexp_kernel: warp per row, branch-free float4; stores tf32-rounded probs.
// ===========================================================================
__global__ __launch_bounds__(256) void rowexp_kernel()
{
    const int tid  = threadIdx.x;
    const int wid  = tid >> 5;
    const int lane = tid & 31;
    const int row  = blockIdx.x * 8 + wid;
    const int q    = row & (S - 1);
    float4* P4 = reinterpret_cast<float4*>(&g_P[(size_t)row * S]);
    const int n4 = (((q >> 7) + 1) << 7) >> 2;

    float m = -1e30f;
    for (int j = lane; j < n4; j += 32) {
        float4 v = P4[j];
        m = fmaxf(m, fmaxf(fmaxf(v.x, v.y), fmaxf(v.z, v.w)));
    }
#pragma unroll
    for (int off = 16; off > 0; off >>= 1)
        m = fmaxf(m, __shfl_xor_sync(0xffffffffu, m, off));

    float l = 0.f;
    for (int j = lane; j < n4; j += 32) {
        float4 v = P4[j];
        float ex = __expf(v.x - m), ey = __expf(v.y - m);
        float ez = __expf(v.z - m), ew = __expf(v.w - m);
        l += (ex + ey) + (ez + ew);
        float4 e = {rtf(ex), rtf(ey), rtf(ez), rtf(ew)};
        P4[j] = e;
    }
#pragma unroll
    for (int off = 16; off > 0; off >>= 1)
        l += __shfl_xor_sync(0xffffffffu, l, off);

    if (lane == 0) g_L[row] = l;
}

// ===========================================================================
// pv_kernel: O[128q x 128d] = (P/l) @ V, causal k-loop, 3-stage ring.
// ldmatrix for P fragments; V via scalar vswz loads (layout not LDSM-able).
// ===========================================================================
__global__ __launch_bounds__(256, 2) void pv_kernel(float* __restrict__ out)
{
    __shared__ uint32_t sP[3][2048];
    __shared__ uint32_t sV[3][2048];

    const int qt    = blockIdx.x;
    const int dc0   = blockIdx.y * 128;
    const int b     = blockIdx.z;
    const int base  = b * S;
    const int qbase = base + qt * 128;

    const int tid  = threadIdx.x;
    const int wid  = tid >> 5;
    const int lane = tid & 31;
    const int wm   = (wid >> 2) * 64;
    const int wn   = (wid & 3) * 32;
    const int lr   = lane >> 2;
    const int lc   = lane & 3;

    const int cm = tid >> 2, cc = tid & 3;
    uint32_t dP[2], dV[2];
    const float *pP[2], *pV[2];
#pragma unroll
    for (int it = 0; it < 2; it++) {
        int m = cm + it * 64;
        int w = (m << 4) + (((cc ^ ((m >> 1) & 3))) << 2);
        dP[it] = smem_u32(&sP[0][0]) + 4 * w;
        pP[it] = g_P + (size_t)(qbase + m) * S + cc * 4;
        int lin = tid + it * 256;
        int k = lin >> 5, c = lin & 31;
        dV[it] = smem_u32(&sV[0][0]) + 4 * vswz(k, c * 4);
        pV[it] = g_V + (size_t)(base + k) * DM + dc0 + c * 4;
    }

    const int lane7 = lane & 7;
    uint32_t adP[4];
    {
        const int akq = (lane >> 4) & 1;
        const int ar0 = wm + lane7 + ((lane >> 3) & 1) * 8;
#pragma unroll
        for (int mi = 0; mi < 4; mi++) {
            int arow = ar0 + mi * 16;
            int h = (arow >> 1) & 3;
            adP[mi] = smem_u32(&sP[0][0]) + 4 * ((arow << 4) + ((akq ^ h) << 2));
        }
    }

    float acc[4][4][4];
#pragma unroll
    for (int mi = 0; mi < 4; mi++)
#pragma unroll
        for (int ni = 0; ni < 4; ni++)
#pragma unroll
            for (int r = 0; r < 4; r++) acc[mi][ni][r] = 0.f;

    const int NT = (qt + 1) * 8;
#pragma unroll
    for (int t = 0; t < 2; t++) {
        const uint32_t off = t * 8192u;
        const int kc = t * 16;
#pragma unroll
        for (int it = 0; it < 2; it++) {
            cpa16(dP[it] + off, pP[it] + kc);
            cpa16(dV[it] + off, pV[it] + (size_t)kc * DM);
        }
        CP_COMMIT();
    }

    int cur = 0;
    for (int kt = 0; kt < NT; kt++) {
        CP_WAIT1();
        __syncthreads();
        {
            int nx = cur + 2; if (nx >= 3) nx -= 3;
            if (kt + 2 < NT) {
                const int kc = (kt + 2) * 16;
                const uint32_t off = nx * 8192u;
#pragma unroll
                for (int it = 0; it < 2; it++) {
                    cpa16(dP[it] + off, pP[it] + kc);
                    cpa16(dV[it] + off, pV[it] + (size_t)kc * DM);
                }
            }
            CP_COMMIT();
        }
        const uint32_t so = cur * 8192u;
        const uint32_t* cV = sV[cur];
#pragma unroll
        for (int ks = 0; ks < 2; ks++) {
            const int k0 = ks * 8;
            const uint32_t kx = ks << 5;
            uint32_t a[4][4], b2[4][2];
#pragma unroll
            for (int mi = 0; mi < 4; mi++) ldsm4(a[mi], (adP[mi] ^ kx) + so);
#pragma unroll
            for (int ni = 0; ni < 4; ni++) {
                int n = wn + ni * 8 + lr;
                b2[ni][0] = cV[vswz(k0 + lc,     n)];
                b2[ni][1] = cV[vswz(k0 + lc + 4, n)];
            }
#pragma unroll
            for (int mi = 0; mi < 4; mi++)
#pragma unroll
                for (int ni = 0; ni < 4; ni++)
                    mma_tf32(acc[mi][ni], a[mi], b2[ni]);
        }
        cur++; if (cur >= 3) cur = 0;
    }

#pragma unroll
    for (int mi = 0; mi < 4; mi++) {
#pragma unroll
        for (int h = 0; h < 2; h++) {
            int qrow = qt * 128 + wm + mi * 16 + lr + h * 8;
            float linv = 1.0f / g_L[base + qrow];
#pragma unroll
            for (int ni = 0; ni < 4; ni++) {
                int col = dc0 + wn + ni * 8 + 2 * lc;
                float2 o = {acc[mi][ni][h * 2 + 0] * linv,
                            acc[mi][ni][h * 2 + 1] * linv};
                *reinterpret_cast<float2*>(
                    &out[(size_t)(base + qrow) * DM + col]) = o;
            }
        }
    }
}

// ===========================================================================
extern "C" void kernel_launch(void* const* d_in, const int* in_sizes, int n_in,
                              void* d_out, int out_size)
{
    const float* X  = (const float*)d_in[0];
    const float* Wq = (const float*)d_in[1];
    const float* bq = (const float*)d_in[2];
    const float* Wk = (const float*)d_in[3];
    const float* bk = (const float*)d_in[4];
    const float* Wv = (const float*)d_in[5];
    const float* bv = (const float*)d_in[6];
    float* out = (float*)d_out;

    round_x_kernel<<<(size_t)ROWS * DM / 4 / 256, 256>>>(X);
    transpose_wv_kernel<<<dim3(32, 32), dim3(32, 8)>>>(Wv);
    prep_qk_kernel<<<dim3(32, 4), dim3(32, 8)>>>(Wq, bq, Wk, bk);
    gemm_tc_kernel<<<dim3(128, 9), 256>>>(bv);              // V + Q|K projections
    score_kernel<<<dim3(136, 8), 256>>>();                  // S = QK^T/8 (causal)
    rowexp_kernel<<<ROWS / 8, 256>>>();                     // softmax (in place)
    pv_kernel<<<dim3(S / 128, DM / 128, B), 256>>>(out);    // O = P V / l
}

// round 15
// speedup vs baseline: 1.3379x; 1.3379x over previous
#include <cuda_runtime.h>
#include <cstdint>

#define B 8
#define S 2048
#define DM 1024
#define DK 64
#define ROWS (B * S)

// ---------------- scratch (device globals; no allocation allowed) ----------
__device__ float g_Xt[(size_t)ROWS * DM];   // X, tf32-rounded (64 MB)
__device__ float g_Q[ROWS * DK];            // tf32-rounded
__device__ float g_K[ROWS * DK];            // tf32-rounded
__device__ float g_V[ROWS * DM];            // tf32-rounded (64 MB)
__device__ float g_L[ROWS];
__device__ float g_P[(size_t)ROWS * S];     // scores, then tf32-rounded probs
__device__ float g_WvT[DM * DM];            // Wv^T, K-major, tf32-rounded
__device__ float g_WqkT[128 * DM];          // [Wq|Wk]^T, K-major, tf32-rounded
__device__ float g_bqk[128];

// ======================= helpers ==========================================
__device__ __forceinline__ uint32_t f2tf32(float f) {
    uint32_t o;
    asm("cvt.rna.tf32.f32 %0, %1;" : "=r"(o) : "f"(f));
    return o;
}
__device__ __forceinline__ float rtf(float f) { return __uint_as_float(f2tf32(f)); }

__device__ __forceinline__ uint32_t smem_u32(const void* p) {
    uint32_t a;
    asm("{ .reg .u64 t; cvta.to.shared.u64 t, %1; cvt.u32.u64 %0, t; }"
        : "=r"(a) : "l"(p));
    return a;
}
__device__ __forceinline__ void cpa16(uint32_t dst, const float* src) {
    asm volatile("cp.async.cg.shared.global [%0], [%1], 16;"
                 :: "r"(dst), "l"(src));
}
#define CP_COMMIT() asm volatile("cp.async.commit_group;" ::: "memory")
#define CP_WAIT1()  asm volatile("cp.async.wait_group 1;" ::: "memory")

// XOR-swizzled word index inside a 128x16-word tile (conflict-free frags)
__device__ __forceinline__ int swz(int m, int k) {
    return (m << 4) + ((((k >> 2) ^ ((m >> 1) & 3)) << 2)) + (k & 3);
}
// V-tile swizzle: 16 rows x 128 words, flip word-index bits 3-4 by (k&3)
__device__ __forceinline__ int vswz(int k, int d) {
    return (k << 7) + (d ^ ((k & 3) << 3));
}

__device__ __forceinline__ void mma_tf32(float c[4], const uint32_t a[4],
                                         const uint32_t b[2]) {
    asm volatile(
        "mma.sync.aligned.m16n8k8.row.col.f32.tf32.tf32.f32 "
        "{%0,%1,%2,%3}, {%4,%5,%6,%7}, {%8,%9}, {%0,%1,%2,%3};"
        : "+f"(c[0]), "+f"(c[1]), "+f"(c[2]), "+f"(c[3])
        : "r"(a[0]), "r"(a[1]), "r"(a[2]), "r"(a[3]), "r"(b[0]), "r"(b[1]));
}

// ===========================================================================
// Prep kernels
// ===========================================================================
__global__ __launch_bounds__(256) void round_x_kernel(const float* __restrict__ X)
{
    size_t i = (size_t)blockIdx.x * 256 + threadIdx.x;
    float4 v = reinterpret_cast<const float4*>(X)[i];
    float4 o = {rtf(v.x), rtf(v.y), rtf(v.z), rtf(v.w)};
    reinterpret_cast<float4*>(g_Xt)[i] = o;
}

__global__ __launch_bounds__(256) void transpose_wv_kernel(const float* __restrict__ Wv)
{
    __shared__ float t[32][33];
    const int k0 = blockIdx.x * 32, n0 = blockIdx.y * 32;
    const int tx = threadIdx.x, ty = threadIdx.y;
#pragma unroll
    for (int i = 0; i < 32; i += 8)
        t[ty + i][tx] = Wv[(k0 + ty + i) * DM + n0 + tx];
    __syncthreads();
#pragma unroll
    for (int i = 0; i < 32; i += 8)
        g_WvT[(n0 + ty + i) * DM + k0 + tx] = rtf(t[tx][ty + i]);
}

__global__ __launch_bounds__(256) void prep_qk_kernel(
    const float* __restrict__ Wq, const float* __restrict__ bq,
    const float* __restrict__ Wk, const float* __restrict__ bk)
{
    __shared__ float t[32][33];
    const int k0 = blockIdx.x * 32, n0 = blockIdx.y * 32;
    const int tx = threadIdx.x, ty = threadIdx.y;
    const int n = n0 + tx;
#pragma unroll
    for (int i = 0; i < 32; i += 8) {
        int k = k0 + ty + i;
        t[ty + i][tx] = (n < 64) ? Wq[k * DK + n] : Wk[k * DK + (n - 64)];
    }
    __syncthreads();
#pragma unroll
    for (int i = 0; i < 32; i += 8)
        g_WqkT[(n0 + ty + i) * DM + k0 + tx] = rtf(t[tx][ty + i]);
    if (blockIdx.x == 0 && blockIdx.y == 0) {
        int id = ty * 32 + tx;
        if (id < 128) g_bqk[id] = (id < 64) ? bq[id] : bk[id - 64];
    }
}

// ===========================================================================
// Merged projections: grid (128, 9).  blockIdx.y < 8 -> V tile (Bt=g_WvT,
// +bv); blockIdx.y == 8 -> Q|K tile (Bt=g_WqkT, +g_bqk, nc=0).
// 3-stage cp.async ring, scalar swizzled fragment loads (R12-proven).
// BM=128 BN=128 BK=16, 8 warps 2x4, warp 64x32.
// ===========================================================================
__global__ __launch_bounds__(256, 2) void gemm_tc_kernel(const float* __restrict__ bv)
{
    __shared__ uint32_t sA[3][2048];   // 24 KB
    __shared__ uint32_t sB[3][2048];   // 24 KB

    const int mode = (blockIdx.y == 8);
    const float* A  = g_Xt;
    const float* Bt = mode ? g_WqkT : g_WvT;

    const int r0   = blockIdx.x * 128;
    const int nc   = mode ? 0 : blockIdx.y * 128;
    const int tid  = threadIdx.x;
    const int wid  = tid >> 5;
    const int lane = tid & 31;
    const int wm   = (wid >> 2) * 64;
    const int wn   = (wid & 3) * 32;
    const int lr   = lane >> 2;
    const int lc   = lane & 3;

    const int cm = tid >> 2, cc = tid & 3;
    uint32_t dA[2], dB[2];
    const float *pA[2], *pB[2];
#pragma unroll
    for (int it = 0; it < 2; it++) {
        int m = cm + it * 64;
        int w = (m << 4) + (((cc ^ ((m >> 1) & 3))) << 2);
        dA[it] = smem_u32(&sA[0][0]) + 4 * w;
        dB[it] = smem_u32(&sB[0][0]) + 4 * w;
        pA[it] = A  + (size_t)(r0 + m) * DM + cc * 4;
        pB[it] = Bt + (size_t)(nc + m) * DM + cc * 4;
    }

    float acc[4][4][4];
#pragma unroll
    for (int mi = 0; mi < 4; mi++)
#pragma unroll
        for (int ni = 0; ni < 4; ni++)
#pragma unroll
            for (int r = 0; r < 4; r++) acc[mi][ni][r] = 0.f;

    const int NT = DM / 16;
#pragma unroll
    for (int t = 0; t < 2; t++) {
        const uint32_t off = t * 8192u;
        const int kc = t * 16;
#pragma unroll
        for (int it = 0; it < 2; it++) {
            cpa16(dA[it] + off, pA[it] + kc);
            cpa16(dB[it] + off, pB[it] + kc);
        }
        CP_COMMIT();
    }

    int cur = 0;
    for (int kt = 0; kt < NT; kt++) {
        CP_WAIT1();
        __syncthreads();
        {
            int nx = cur + 2; if (nx >= 3) nx -= 3;
            if (kt + 2 < NT) {
                const int kc = (kt + 2) * 16;
                const uint32_t off = nx * 8192u;
#pragma unroll
                for (int it = 0; it < 2; it++) {
                    cpa16(dA[it] + off, pA[it] + kc);
                    cpa16(dB[it] + off, pB[it] + kc);
                }
            }
            CP_COMMIT();
        }
        const uint32_t* cA = sA[cur];
        const uint32_t* cB = sB[cur];
#pragma unroll
        for (int ks = 0; ks < 2; ks++) {
            const int k0 = ks * 8;
            uint32_t a[4][4], b[4][2];
#pragma unroll
            for (int mi = 0; mi < 4; mi++) {
                int row = wm + mi * 16 + lr;
                a[mi][0] = cA[swz(row,     k0 + lc)];
                a[mi][1] = cA[swz(row + 8, k0 + lc)];
                a[mi][2] = cA[swz(row,     k0 + lc + 4)];
                a[mi][3] = cA[swz(row + 8, k0 + lc + 4)];
            }
#pragma unroll
            for (int ni = 0; ni < 4; ni++) {
                int n = wn + ni * 8 + lr;
                b[ni][0] = cB[swz(n, k0 + lc)];
                b[ni][1] = cB[swz(n, k0 + lc + 4)];
            }
#pragma unroll
            for (int mi = 0; mi < 4; mi++)
#pragma unroll
                for (int ni = 0; ni < 4; ni++)
                    mma_tf32(acc[mi][ni], a[mi], b[ni]);
        }
        cur++; if (cur >= 3) cur = 0;
    }

#pragma unroll
    for (int mi = 0; mi < 4; mi++) {
#pragma unroll
        for (int ni = 0; ni < 4; ni++) {
#pragma unroll
            for (int h = 0; h < 2; h++) {
                int row = r0 + wm + mi * 16 + lr + h * 8;
                int col = wn + ni * 8 + 2 * lc;
                float v0 = acc[mi][ni][h * 2 + 0];
                float v1 = acc[mi][ni][h * 2 + 1];
                if (!mode) {
                    float2 o = {rtf(v0 + bv[nc + col]), rtf(v1 + bv[nc + col + 1])};
                    *reinterpret_cast<float2*>(&g_V[(size_t)row * DM + nc + col]) = o;
                } else {
                    float2 o = {rtf(v0 + g_bqk[col]), rtf(v1 + g_bqk[col + 1])};
                    if (col < 64)
                        *reinterpret_cast<float2*>(&g_Q[(size_t)row * DK + col]) = o;
                    else
                        *reinterpret_cast<float2*>(&g_K[(size_t)row * DK + (col - 64)]) = o;
                }
            }
        }
    }
}

// ===========================================================================
// score_kernel: one 128x128 causal tile of S = Q K^T / 8 per CTA (raw fp32,
// masked = -1e30).  3-stage ring, NT = 4 (DK=64, BK=16), scalar frags.
// ===========================================================================
__global__ __launch_bounds__(256, 2) void score_kernel()
{
    __shared__ uint32_t sA[3][2048];
    __shared__ uint32_t sB[3][2048];

    int i = blockIdx.x;
    int qt = (int)((sqrtf(8.f * (float)i + 1.f) - 1.f) * 0.5f);
    while ((qt + 1) * (qt + 2) / 2 <= i) qt++;
    while (qt * (qt + 1) / 2 > i) qt--;
    const int kt = i - qt * (qt + 1) / 2;

    const int b     = blockIdx.y;
    const int qbase = b * S + qt * 128;
    const int kbase = b * S + kt * 128;

    const int tid  = threadIdx.x;
    const int wid  = tid >> 5;
    const int lane = tid & 31;
    const int wm   = (wid >> 2) * 64;
    const int wn   = (wid & 3) * 32;
    const int lr   = lane >> 2;
    const int lc   = lane & 3;

    const int cm = tid >> 2, cc = tid & 3;
    uint32_t dA[2], dB[2];
    const float *pA[2], *pB[2];
#pragma unroll
    for (int it = 0; it < 2; it++) {
        int m = cm + it * 64;
        int w = (m << 4) + (((cc ^ ((m >> 1) & 3))) << 2);
        dA[it] = smem_u32(&sA[0][0]) + 4 * w;
        dB[it] = smem_u32(&sB[0][0]) + 4 * w;
        pA[it] = g_Q + (size_t)(qbase + m) * DK + cc * 4;
        pB[it] = g_K + (size_t)(kbase + m) * DK + cc * 4;
    }

    float acc[4][4][4];
#pragma unroll
    for (int mi = 0; mi < 4; mi++)
#pragma unroll
        for (int ni = 0; ni < 4; ni++)
#pragma unroll
            for (int r = 0; r < 4; r++) acc[mi][ni][r] = 0.f;

    const int NT = DK / 16;   // 4
#pragma unroll
    for (int t = 0; t < 2; t++) {
        const uint32_t off = t * 8192u;
        const int kc = t * 16;
#pragma unroll
        for (int it = 0; it < 2; it++) {
            cpa16(dA[it] + off, pA[it] + kc);
            cpa16(dB[it] + off, pB[it] + kc);
        }
        CP_COMMIT();
    }

    int cur = 0;
    for (int ktile = 0; ktile < NT; ktile++) {
        CP_WAIT1();
        __syncthreads();
        {
            int nx = cur + 2; if (nx >= 3) nx -= 3;
            if (ktile + 2 < NT) {
                const int kc = (ktile + 2) * 16;
                const uint32_t off = nx * 8192u;
#pragma unroll
                for (int it = 0; it < 2; it++) {
                    cpa16(dA[it] + off, pA[it] + kc);
                    cpa16(dB[it] + off, pB[it] + kc);
                }
            }
            CP_COMMIT();
        }
        const uint32_t* cA = sA[cur];
        const uint32_t* cB = sB[cur];
#pragma unroll
        for (int ks = 0; ks < 2; ks++) {
            const int k0 = ks * 8;
            uint32_t a[4][4], b2[4][2];
#pragma unroll
            for (int mi = 0; mi < 4; mi++) {
                int row = wm + mi * 16 + lr;
                a[mi][0] = cA[swz(row,     k0 + lc)];
                a[mi][1] = cA[swz(row + 8, k0 + lc)];
                a[mi][2] = cA[swz(row,     k0 + lc + 4)];
                a[mi][3] = cA[swz(row + 8, k0 + lc + 4)];
            }
#pragma unroll
            for (int ni = 0; ni < 4; ni++) {
                int n = wn + ni * 8 + lr;
                b2[ni][0] = cB[swz(n, k0 + lc)];
                b2[ni][1] = cB[swz(n, k0 + lc + 4)];
            }
#pragma unroll
            for (int mi = 0; mi < 4; mi++)
#pragma unroll
                for (int ni = 0; ni < 4; ni++)
                    mma_tf32(acc[mi][ni], a[mi], b2[ni]);
        }
        cur++; if (cur >= 3) cur = 0;
    }

#pragma unroll
    for (int mi = 0; mi < 4; mi++) {
#pragma unroll
        for (int ni = 0; ni < 4; ni++) {
#pragma unroll
            for (int h = 0; h < 2; h++) {
                int qrow = qt * 128 + wm + mi * 16 + lr + h * 8;
                int kcol = kt * 128 + wn + ni * 8 + 2 * lc;
                float v0 = acc[mi][ni][h * 2 + 0] * 0.125f;
                float v1 = acc[mi][ni][h * 2 + 1] * 0.125f;
                if (kcol > qrow)     v0 = -1e30f;
                if (kcol + 1 > qrow) v1 = -1e30f;
                float2 o = {v0, v1};
                *reinterpret_cast<float2*>(
                    &g_P[(size_t)(b * S + qrow) * S + kcol]) = o;
            }
        }
    }
}

// ===========================================================================
// rowexp_kernel: warp per row, branch-free float4; stores tf32-rounded probs.
// ===========================================================================
__global__ __launch_bounds__(256) void rowexp_kernel()
{
    const int tid  = threadIdx.x;
    const int wid  = tid >> 5;
    const int lane = tid & 31;
    const int row  = blockIdx.x * 8 + wid;
    const int q    = row & (S - 1);
    float4* P4 = reinterpret_cast<float4*>(&g_P[(size_t)row * S]);
    const int n4 = (((q >> 7) + 1) << 7) >> 2;

    float m = -1e30f;
    for (int j = lane; j < n4; j += 32) {
        float4 v = P4[j];
        m = fmaxf(m, fmaxf(fmaxf(v.x, v.y), fmaxf(v.z, v.w)));
    }
#pragma unroll
    for (int off = 16; off > 0; off >>= 1)
        m = fmaxf(m, __shfl_xor_sync(0xffffffffu, m, off));

    float l = 0.f;
    for (int j = lane; j < n4; j += 32) {
        float4 v = P4[j];
        float ex = __expf(v.x - m), ey = __expf(v.y - m);
        float ez = __expf(v.z - m), ew = __expf(v.w - m);
        l += (ex + ey) + (ez + ew);
        float4 e = {rtf(ex), rtf(ey), rtf(ez), rtf(ew)};
        P4[j] = e;
    }
#pragma unroll
    for (int off = 16; off > 0; off >>= 1)
        l += __shfl_xor_sync(0xffffffffu, l, off);

    if (lane == 0) g_L[row] = l;
}

// ===========================================================================
// pv_kernel: O[128q x 128d] = (P/l) @ V, causal k-loop, 3-stage ring.
// Grid (dc, qt, b) with dc FASTEST so the 8 CTAs sharing a P row-block are
// co-resident -> P re-reads hit L2.  Scalar frags (R12-proven).
// ===========================================================================
__global__ __launch_bounds__(256, 2) void pv_kernel(float* __restrict__ out)
{
    __shared__ uint32_t sP[3][2048];
    __shared__ uint32_t sV[3][2048];

    const int qt    = blockIdx.y;
    const int dc0   = blockIdx.x * 128;
    const int b     = blockIdx.z;
    const int base  = b * S;
    const int qbase = base + qt * 128;

    const int tid  = threadIdx.x;
    const int wid  = tid >> 5;
    const int lane = tid & 31;
    const int wm   = (wid >> 2) * 64;
    const int wn   = (wid & 3) * 32;
    const int lr   = lane >> 2;
    const int lc   = lane & 3;

    const int cm = tid >> 2, cc = tid & 3;
    uint32_t dP[2], dV[2];
    const float *pP[2], *pV[2];
#pragma unroll
    for (int it = 0; it < 2; it++) {
        int m = cm + it * 64;
        int w = (m << 4) + (((cc ^ ((m >> 1) & 3))) << 2);
        dP[it] = smem_u32(&sP[0][0]) + 4 * w;
        pP[it] = g_P + (size_t)(qbase + m) * S + cc * 4;
        int lin = tid + it * 256;
        int k = lin >> 5, c = lin & 31;
        dV[it] = smem_u32(&sV[0][0]) + 4 * vswz(k, c * 4);
        pV[it] = g_V + (size_t)(base + k) * DM + dc0 + c * 4;
    }

    float acc[4][4][4];
#pragma unroll
    for (int mi = 0; mi < 4; mi++)
#pragma unroll
        for (int ni = 0; ni < 4; ni++)
#pragma unroll
            for (int r = 0; r < 4; r++) acc[mi][ni][r] = 0.f;

    const int NT = (qt + 1) * 8;
#pragma unroll
    for (int t = 0; t < 2; t++) {
        const uint32_t off = t * 8192u;
        const int kc = t * 16;
#pragma unroll
        for (int it = 0; it < 2; it++) {
            cpa16(dP[it] + off, pP[it] + kc);
            cpa16(dV[it] + off, pV[it] + (size_t)kc * DM);
        }
        CP_COMMIT();
    }

    int cur = 0;
    for (int kt = 0; kt < NT; kt++) {
        CP_WAIT1();
        __syncthreads();
        {
            int nx = cur + 2; if (nx >= 3) nx -= 3;
            if (kt + 2 < NT) {
                const int kc = (kt + 2) * 16;
                const uint32_t off = nx * 8192u;
#pragma unroll
                for (int it = 0; it < 2; it++) {
                    cpa16(dP[it] + off, pP[it] + kc);
                    cpa16(dV[it] + off, pV[it] + (size_t)kc * DM);
                }
            }
            CP_COMMIT();
        }
        const uint32_t* cP = sP[cur];
        const uint32_t* cV = sV[cur];
#pragma unroll
        for (int ks = 0; ks < 2; ks++) {
            const int k0 = ks * 8;
            uint32_t a[4][4], b2[4][2];
#pragma unroll
            for (int mi = 0; mi < 4; mi++) {
                int row = wm + mi * 16 + lr;
                a[mi][0] = cP[swz(row,     k0 + lc)];
                a[mi][1] = cP[swz(row + 8, k0 + lc)];
                a[mi][2] = cP[swz(row,     k0 + lc + 4)];
                a[mi][3] = cP[swz(row + 8, k0 + lc + 4)];
            }
#pragma unroll
            for (int ni = 0; ni < 4; ni++) {
                int n = wn + ni * 8 + lr;
                b2[ni][0] = cV[vswz(k0 + lc,     n)];
                b2[ni][1] = cV[vswz(k0 + lc + 4, n)];
            }
#pragma unroll
            for (int mi = 0; mi < 4; mi++)
#pragma unroll
                for (int ni = 0; ni < 4; ni++)
                    mma_tf32(acc[mi][ni], a[mi], b2[ni]);
        }
        cur++; if (cur >= 3) cur = 0;
    }

#pragma unroll
    for (int mi = 0; mi < 4; mi++) {
#pragma unroll
        for (int h = 0; h < 2; h++) {
            int qrow = qt * 128 + wm + mi * 16 + lr + h * 8;
            float linv = 1.0f / g_L[base + qrow];
#pragma unroll
            for (int ni = 0; ni < 4; ni++) {
                int col = dc0 + wn + ni * 8 + 2 * lc;
                float2 o = {acc[mi][ni][h * 2 + 0] * linv,
                            acc[mi][ni][h * 2 + 1] * linv};
                *reinterpret_cast<float2*>(
                    &out[(size_t)(base + qrow) * DM + col]) = o;
            }
        }
    }
}

// ===========================================================================
extern "C" void kernel_launch(void* const* d_in, const int* in_sizes, int n_in,
                              void* d_out, int out_size)
{
    const float* X  = (const float*)d_in[0];
    const float* Wq = (const float*)d_in[1];
    const float* bq = (const float*)d_in[2];
    const float* Wk = (const float*)d_in[3];
    const float* bk = (const float*)d_in[4];
    const float* Wv = (const float*)d_in[5];
    const float* bv = (const float*)d_in[6];
    float* out = (float*)d_out;

    round_x_kernel<<<(size_t)ROWS * DM / 4 / 256, 256>>>(X);
    transpose_wv_kernel<<<dim3(32, 32), dim3(32, 8)>>>(Wv);
    prep_qk_kernel<<<dim3(32, 4), dim3(32, 8)>>>(Wq, bq, Wk, bk);
    gemm_tc_kernel<<<dim3(128, 9), 256>>>(bv);              // V + Q|K projections
    score_kernel<<<dim3(136, 8), 256>>>();                  // S = QK^T/8 (causal)
    rowexp_kernel<<<ROWS / 8, 256>>>();                     // softmax (in place)
    pv_kernel<<<dim3(DM / 128, S / 128, B), 256>>>(out);    // O = P V / l
}

// round 16
// speedup vs baseline: 1.3721x; 1.0255x over previous
#include <cuda_runtime.h>
#include <cstdint>

#define B 8
#define S 2048
#define DM 1024
#define DK 64
#define ROWS (B * S)

// ---------------- scratch (device globals; no allocation allowed) ----------
__device__ float g_Xt[(size_t)ROWS * DM];   // X, tf32-rounded (64 MB)
__device__ float g_Q[ROWS * DK];            // tf32-rounded
__device__ float g_K[ROWS * DK];            // tf32-rounded
__device__ float g_V[ROWS * DM];            // tf32-rounded (64 MB)
__device__ float g_L[ROWS];
__device__ float g_P[(size_t)ROWS * S];     // scores, then tf32-rounded probs
__device__ float g_WvT[DM * DM];            // Wv^T, K-major, tf32-rounded
__device__ float g_WqkT[128 * DM];          // [Wq|Wk]^T, K-major, tf32-rounded
__device__ float g_bqk[128];

// ======================= helpers ==========================================
__device__ __forceinline__ uint32_t f2tf32(float f) {
    uint32_t o;
    asm("cvt.rna.tf32.f32 %0, %1;" : "=r"(o) : "f"(f));
    return o;
}
__device__ __forceinline__ float rtf(float f) { return __uint_as_float(f2tf32(f)); }

__device__ __forceinline__ uint32_t smem_u32(const void* p) {
    uint32_t a;
    asm("{ .reg .u64 t; cvta.to.shared.u64 t, %1; cvt.u32.u64 %0, t; }"
        : "=r"(a) : "l"(p));
    return a;
}
__device__ __forceinline__ void cpa16(uint32_t dst, const float* src) {
    asm volatile("cp.async.cg.shared.global [%0], [%1], 16;"
                 :: "r"(dst), "l"(src));
}
#define CP_COMMIT() asm volatile("cp.async.commit_group;" ::: "memory")
#define CP_WAIT1()  asm volatile("cp.async.wait_group 1;" ::: "memory")

// XOR-swizzled word index inside a 128x16-word tile (conflict-free frags)
__device__ __forceinline__ int swz(int m, int k) {
    return (m << 4) + ((((k >> 2) ^ ((m >> 1) & 3)) << 2)) + (k & 3);
}
// V-tile swizzle: 16 rows x 128 words, flip word-index bits 3-4 by (k&3)
__device__ __forceinline__ int vswz(int k, int d) {
    return (k << 7) + (d ^ ((k & 3) << 3));
}

__device__ __forceinline__ void mma_tf32(float c[4], const uint32_t a[4],
                                         const uint32_t b[2]) {
    asm volatile(
        "mma.sync.aligned.m16n8k8.row.col.f32.tf32.tf32.f32 "
        "{%0,%1,%2,%3}, {%4,%5,%6,%7}, {%8,%9}, {%0,%1,%2,%3};"
        : "+f"(c[0]), "+f"(c[1]), "+f"(c[2]), "+f"(c[3])
        : "r"(a[0]), "r"(a[1]), "r"(a[2]), "r"(a[3]), "r"(b[0]), "r"(b[1]));
}

// ===========================================================================
// Prep kernels
// ===========================================================================
__global__ __launch_bounds__(256) void round_x_kernel(const float* __restrict__ X)
{
    size_t i = (size_t)blockIdx.x * 256 + threadIdx.x;
    float4 v = reinterpret_cast<const float4*>(X)[i];
    float4 o = {rtf(v.x), rtf(v.y), rtf(v.z), rtf(v.w)};
    reinterpret_cast<float4*>(g_Xt)[i] = o;
}

__global__ __launch_bounds__(256) void transpose_wv_kernel(const float* __restrict__ Wv)
{
    __shared__ float t[32][33];
    const int k0 = blockIdx.x * 32, n0 = blockIdx.y * 32;
    const int tx = threadIdx.x, ty = threadIdx.y;
#pragma unroll
    for (int i = 0; i < 32; i += 8)
        t[ty + i][tx] = Wv[(k0 + ty + i) * DM + n0 + tx];
    __syncthreads();
#pragma unroll
    for (int i = 0; i < 32; i += 8)
        g_WvT[(n0 + ty + i) * DM + k0 + tx] = rtf(t[tx][ty + i]);
}

__global__ __launch_bounds__(256) void prep_qk_kernel(
    const float* __restrict__ Wq, const float* __restrict__ bq,
    const float* __restrict__ Wk, const float* __restrict__ bk)
{
    __shared__ float t[32][33];
    const int k0 = blockIdx.x * 32, n0 = blockIdx.y * 32;
    const int tx = threadIdx.x, ty = threadIdx.y;
    const int n = n0 + tx;
#pragma unroll
    for (int i = 0; i < 32; i += 8) {
        int k = k0 + ty + i;
        t[ty + i][tx] = (n < 64) ? Wq[k * DK + n] : Wk[k * DK + (n - 64)];
    }
    __syncthreads();
#pragma unroll
    for (int i = 0; i < 32; i += 8)
        g_WqkT[(n0 + ty + i) * DM + k0 + tx] = rtf(t[tx][ty + i]);
    if (blockIdx.x == 0 && blockIdx.y == 0) {
        int id = ty * 32 + tx;
        if (id < 128) g_bqk[id] = (id < 64) ? bq[id] : bk[id - 64];
    }
}

// ===========================================================================
// Merged projections: grid (128, 9).  blockIdx.y < 8 -> V tile (Bt=g_WvT,
// +bv); blockIdx.y == 8 -> Q|K tile (Bt=g_WqkT, +g_bqk, nc=0).
// 3-stage cp.async ring, scalar swizzled fragment loads (R12-proven).
// BM=128 BN=128 BK=16, 8 warps 2x4, warp 64x32.
// ===========================================================================
__global__ __launch_bounds__(256, 2) void gemm_tc_kernel(const float* __restrict__ bv)
{
    __shared__ uint32_t sA[3][2048];   // 24 KB
    __shared__ uint32_t sB[3][2048];   // 24 KB

    const int mode = (blockIdx.y == 8);
    const float* A  = g_Xt;
    const float* Bt = mode ? g_WqkT : g_WvT;

    const int r0   = blockIdx.x * 128;
    const int nc   = mode ? 0 : blockIdx.y * 128;
    const int tid  = threadIdx.x;
    const int wid  = tid >> 5;
    const int lane = tid & 31;
    const int wm   = (wid >> 2) * 64;
    const int wn   = (wid & 3) * 32;
    const int lr   = lane >> 2;
    const int lc   = lane & 3;

    const int cm = tid >> 2, cc = tid & 3;
    uint32_t dA[2], dB[2];
    const float *pA[2], *pB[2];
#pragma unroll
    for (int it = 0; it < 2; it++) {
        int m = cm + it * 64;
        int w = (m << 4) + (((cc ^ ((m >> 1) & 3))) << 2);
        dA[it] = smem_u32(&sA[0][0]) + 4 * w;
        dB[it] = smem_u32(&sB[0][0]) + 4 * w;
        pA[it] = A  + (size_t)(r0 + m) * DM + cc * 4;
        pB[it] = Bt + (size_t)(nc + m) * DM + cc * 4;
    }

    float acc[4][4][4];
#pragma unroll
    for (int mi = 0; mi < 4; mi++)
#pragma unroll
        for (int ni = 0; ni < 4; ni++)
#pragma unroll
            for (int r = 0; r < 4; r++) acc[mi][ni][r] = 0.f;

    const int NT = DM / 16;
#pragma unroll
    for (int t = 0; t < 2; t++) {
        const uint32_t off = t * 8192u;
        const int kc = t * 16;
#pragma unroll
        for (int it = 0; it < 2; it++) {
            cpa16(dA[it] + off, pA[it] + kc);
            cpa16(dB[it] + off, pB[it] + kc);
        }
        CP_COMMIT();
    }

    int cur = 0;
    for (int kt = 0; kt < NT; kt++) {
        CP_WAIT1();
        __syncthreads();
        {
            int nx = cur + 2; if (nx >= 3) nx -= 3;
            if (kt + 2 < NT) {
                const int kc = (kt + 2) * 16;
                const uint32_t off = nx * 8192u;
#pragma unroll
                for (int it = 0; it < 2; it++) {
                    cpa16(dA[it] + off, pA[it] + kc);
                    cpa16(dB[it] + off, pB[it] + kc);
                }
            }
            CP_COMMIT();
        }
        const uint32_t* cA = sA[cur];
        const uint32_t* cB = sB[cur];
#pragma unroll
        for (int ks = 0; ks < 2; ks++) {
            const int k0 = ks * 8;
            uint32_t a[4][4], b[4][2];
#pragma unroll
            for (int mi = 0; mi < 4; mi++) {
                int row = wm + mi * 16 + lr;
                a[mi][0] = cA[swz(row,     k0 + lc)];
                a[mi][1] = cA[swz(row + 8, k0 + lc)];
                a[mi][2] = cA[swz(row,     k0 + lc + 4)];
                a[mi][3] = cA[swz(row + 8, k0 + lc + 4)];
            }
#pragma unroll
            for (int ni = 0; ni < 4; ni++) {
                int n = wn + ni * 8 + lr;
                b[ni][0] = cB[swz(n, k0 + lc)];
                b[ni][1] = cB[swz(n, k0 + lc + 4)];
            }
#pragma unroll
            for (int mi = 0; mi < 4; mi++)
#pragma unroll
                for (int ni = 0; ni < 4; ni++)
                    mma_tf32(acc[mi][ni], a[mi], b[ni]);
        }
        cur++; if (cur >= 3) cur = 0;
    }

#pragma unroll
    for (int mi = 0; mi < 4; mi++) {
#pragma unroll
        for (int ni = 0; ni < 4; ni++) {
#pragma unroll
            for (int h = 0; h < 2; h++) {
                int row = r0 + wm + mi * 16 + lr + h * 8;
                int col = wn + ni * 8 + 2 * lc;
                float v0 = acc[mi][ni][h * 2 + 0];
                float v1 = acc[mi][ni][h * 2 + 1];
                if (!mode) {
                    float2 o = {rtf(v0 + bv[nc + col]), rtf(v1 + bv[nc + col + 1])};
                    *reinterpret_cast<float2*>(&g_V[(size_t)row * DM + nc + col]) = o;
                } else {
                    float2 o = {rtf(v0 + g_bqk[col]), rtf(v1 + g_bqk[col + 1])};
                    if (col < 64)
                        *reinterpret_cast<float2*>(&g_Q[(size_t)row * DK + col]) = o;
                    else
                        *reinterpret_cast<float2*>(&g_K[(size_t)row * DK + (col - 64)]) = o;
                }
            }
        }
    }
}

// ===========================================================================
// score_kernel: one 128x128 causal tile of S = Q K^T / 8 per CTA (raw fp32,
// masked = -1e30).  3-stage ring, NT = 4 (DK=64, BK=16), scalar frags.
// ===========================================================================
__global__ __launch_bounds__(256, 2) void score_kernel()
{
    __shared__ uint32_t sA[3][2048];
    __shared__ uint32_t sB[3][2048];

    int i = blockIdx.x;
    int qt = (int)((sqrtf(8.f * (float)i + 1.f) - 1.f) * 0.5f);
    while ((qt + 1) * (qt + 2) / 2 <= i) qt++;
    while (qt * (qt + 1) / 2 > i) qt--;
    const int kt = i - qt * (qt + 1) / 2;

    const int b     = blockIdx.y;
    const int qbase = b * S + qt * 128;
    const int kbase = b * S + kt * 128;

    const int tid  = threadIdx.x;
    const int wid  = tid >> 5;
    const int lane = tid & 31;
    const int wm   = (wid >> 2) * 64;
    const int wn   = (wid & 3) * 32;
    const int lr   = lane >> 2;
    const int lc   = lane & 3;

    const int cm = tid >> 2, cc = tid & 3;
    uint32_t dA[2], dB[2];
    const float *pA[2], *pB[2];
#pragma unroll
    for (int it = 0; it < 2; it++) {
        int m = cm + it * 64;
        int w = (m << 4) + (((cc ^ ((m >> 1) & 3))) << 2);
        dA[it] = smem_u32(&sA[0][0]) + 4 * w;
        dB[it] = smem_u32(&sB[0][0]) + 4 * w;
        pA[it] = g_Q + (size_t)(qbase + m) * DK + cc * 4;
        pB[it] = g_K + (size_t)(kbase + m) * DK + cc * 4;
    }

    float acc[4][4][4];
#pragma unroll
    for (int mi = 0; mi < 4; mi++)
#pragma unroll
        for (int ni = 0; ni < 4; ni++)
#pragma unroll
            for (int r = 0; r < 4; r++) acc[mi][ni][r] = 0.f;

    const int NT = DK / 16;   // 4
#pragma unroll
    for (int t = 0; t < 2; t++) {
        const uint32_t off = t * 8192u;
        const int kc = t * 16;
#pragma unroll
        for (int it = 0; it < 2; it++) {
            cpa16(dA[it] + off, pA[it] + kc);
            cpa16(dB[it] + off, pB[it] + kc);
        }
        CP_COMMIT();
    }

    int cur = 0;
    for (int ktile = 0; ktile < NT; ktile++) {
        CP_WAIT1();
        __syncthreads();
        {
            int nx = cur + 2; if (nx >= 3) nx -= 3;
            if (ktile + 2 < NT) {
                const int kc = (ktile + 2) * 16;
                const uint32_t off = nx * 8192u;
#pragma unroll
                for (int it = 0; it < 2; it++) {
                    cpa16(dA[it] + off, pA[it] + kc);
                    cpa16(dB[it] + off, pB[it] + kc);
                }
            }
            CP_COMMIT();
        }
        const uint32_t* cA = sA[cur];
        const uint32_t* cB = sB[cur];
#pragma unroll
        for (int ks = 0; ks < 2; ks++) {
            const int k0 = ks * 8;
            uint32_t a[4][4], b2[4][2];
#pragma unroll
            for (int mi = 0; mi < 4; mi++) {
                int row = wm + mi * 16 + lr;
                a[mi][0] = cA[swz(row,     k0 + lc)];
                a[mi][1] = cA[swz(row + 8, k0 + lc)];
                a[mi][2] = cA[swz(row,     k0 + lc + 4)];
                a[mi][3] = cA[swz(row + 8, k0 + lc + 4)];
            }
#pragma unroll
            for (int ni = 0; ni < 4; ni++) {
                int n = wn + ni * 8 + lr;
                b2[ni][0] = cB[swz(n, k0 + lc)];
                b2[ni][1] = cB[swz(n, k0 + lc + 4)];
            }
#pragma unroll
            for (int mi = 0; mi < 4; mi++)
#pragma unroll
                for (int ni = 0; ni < 4; ni++)
                    mma_tf32(acc[mi][ni], a[mi], b2[ni]);
        }
        cur++; if (cur >= 3) cur = 0;
    }

#pragma unroll
    for (int mi = 0; mi < 4; mi++) {
#pragma unroll
        for (int ni = 0; ni < 4; ni++) {
#pragma unroll
            for (int h = 0; h < 2; h++) {
                int qrow = qt * 128 + wm + mi * 16 + lr + h * 8;
                int kcol = kt * 128 + wn + ni * 8 + 2 * lc;
                float v0 = acc[mi][ni][h * 2 + 0] * 0.125f;
                float v1 = acc[mi][ni][h * 2 + 1] * 0.125f;
                if (kcol > qrow)     v0 = -1e30f;
                if (kcol + 1 > qrow) v1 = -1e30f;
                float2 o = {v0, v1};
                *reinterpret_cast<float2*>(
                    &g_P[(size_t)(b * S + qrow) * S + kcol]) = o;
            }
        }
    }
}

// ===========================================================================
// rowexp_kernel: warp per row, branch-free float4; stores tf32-rounded probs.
// ===========================================================================
__global__ __launch_bounds__(256) void rowexp_kernel()
{
    const int tid  = threadIdx.x;
    const int wid  = tid >> 5;
    const int lane = tid & 31;
    const int row  = blockIdx.x * 8 + wid;
    const int q    = row & (S - 1);
    float4* P4 = reinterpret_cast<float4*>(&g_P[(size_t)row * S]);
    const int n4 = (((q >> 7) + 1) << 7) >> 2;

    float m = -1e30f;
    for (int j = lane; j < n4; j += 32) {
        float4 v = P4[j];
        m = fmaxf(m, fmaxf(fmaxf(v.x, v.y), fmaxf(v.z, v.w)));
    }
#pragma unroll
    for (int off = 16; off > 0; off >>= 1)
        m = fmaxf(m, __shfl_xor_sync(0xffffffffu, m, off));

    float l = 0.f;
    for (int j = lane; j < n4; j += 32) {
        float4 v = P4[j];
        float ex = __expf(v.x - m), ey = __expf(v.y - m);
        float ez = __expf(v.z - m), ew = __expf(v.w - m);
        l += (ex + ey) + (ez + ew);
        float4 e = {rtf(ex), rtf(ey), rtf(ez), rtf(ew)};
        P4[j] = e;
    }
#pragma unroll
    for (int off = 16; off > 0; off >>= 1)
        l += __shfl_xor_sync(0xffffffffu, l, off);

    if (lane == 0) g_L[row] = l;
}

// ===========================================================================
// pv_kernel: O[128q x 128d] = (P/l) @ V, causal k-loop, 3-stage ring.
// Grid (qt, dc, b) with qt FASTEST (R12-proven balance), processed in
// descending-work order (LPT): qt = gridDim.x-1-blockIdx.x.
// ===========================================================================
__global__ __launch_bounds__(256, 2) void pv_kernel(float* __restrict__ out)
{
    __shared__ uint32_t sP[3][2048];
    __shared__ uint32_t sV[3][2048];

    const int qt    = gridDim.x - 1 - blockIdx.x;   // longest first
    const int dc0   = blockIdx.y * 128;
    const int b     = blockIdx.z;
    const int base  = b * S;
    const int qbase = base + qt * 128;

    const int tid  = threadIdx.x;
    const int wid  = tid >> 5;
    const int lane = tid & 31;
    const int wm   = (wid >> 2) * 64;
    const int wn   = (wid & 3) * 32;
    const int lr   = lane >> 2;
    const int lc   = lane & 3;

    const int cm = tid >> 2, cc = tid & 3;
    uint32_t dP[2], dV[2];
    const float *pP[2], *pV[2];
#pragma unroll
    for (int it = 0; it < 2; it++) {
        int m = cm + it * 64;
        int w = (m << 4) + (((cc ^ ((m >> 1) & 3))) << 2);
        dP[it] = smem_u32(&sP[0][0]) + 4 * w;
        pP[it] = g_P + (size_t)(qbase + m) * S + cc * 4;
        int lin = tid + it * 256;
        int k = lin >> 5, c = lin & 31;
        dV[it] = smem_u32(&sV[0][0]) + 4 * vswz(k, c * 4);
        pV[it] = g_V + (size_t)(base + k) * DM + dc0 + c * 4;
    }

    float acc[4][4][4];
#pragma unroll
    for (int mi = 0; mi < 4; mi++)
#pragma unroll
        for (int ni = 0; ni < 4; ni++)
#pragma unroll
            for (int r = 0; r < 4; r++) acc[mi][ni][r] = 0.f;

    const int NT = (qt + 1) * 8;
#pragma unroll
    for (int t = 0; t < 2; t++) {
        const uint32_t off = t * 8192u;
        const int kc = t * 16;
#pragma unroll
        for (int it = 0; it < 2; it++) {
            cpa16(dP[it] + off, pP[it] + kc);
            cpa16(dV[it] + off, pV[it] + (size_t)kc * DM);
        }
        CP_COMMIT();
    }

    int cur = 0;
    for (int kt = 0; kt < NT; kt++) {
        CP_WAIT1();
        __syncthreads();
        {
            int nx = cur + 2; if (nx >= 3) nx -= 3;
            if (kt + 2 < NT) {
                const int kc = (kt + 2) * 16;
                const uint32_t off = nx * 8192u;
#pragma unroll
                for (int it = 0; it < 2; it++) {
                    cpa16(dP[it] + off, pP[it] + kc);
                    cpa16(dV[it] + off, pV[it] + (size_t)kc * DM);
                }
            }
            CP_COMMIT();
        }
        const uint32_t* cP = sP[cur];
        const uint32_t* cV = sV[cur];
#pragma unroll
        for (int ks = 0; ks < 2; ks++) {
            const int k0 = ks * 8;
            uint32_t a[4][4], b2[4][2];
#pragma unroll
            for (int mi = 0; mi < 4; mi++) {
                int row = wm + mi * 16 + lr;
                a[mi][0] = cP[swz(row,     k0 + lc)];
                a[mi][1] = cP[swz(row + 8, k0 + lc)];
                a[mi][2] = cP[swz(row,     k0 + lc + 4)];
                a[mi][3] = cP[swz(row + 8, k0 + lc + 4)];
            }
#pragma unroll
            for (int ni = 0; ni < 4; ni++) {
                int n = wn + ni * 8 + lr;
                b2[ni][0] = cV[vswz(k0 + lc,     n)];
                b2[ni][1] = cV[vswz(k0 + lc + 4, n)];
            }
#pragma unroll
            for (int mi = 0; mi < 4; mi++)
#pragma unroll
                for (int ni = 0; ni < 4; ni++)
                    mma_tf32(acc[mi][ni], a[mi], b2[ni]);
        }
        cur++; if (cur >= 3) cur = 0;
    }

#pragma unroll
    for (int mi = 0; mi < 4; mi++) {
#pragma unroll
        for (int h = 0; h < 2; h++) {
            int qrow = qt * 128 + wm + mi * 16 + lr + h * 8;
            float linv = 1.0f / g_L[base + qrow];
#pragma unroll
            for (int ni = 0; ni < 4; ni++) {
                int col = dc0 + wn + ni * 8 + 2 * lc;
                float2 o = {acc[mi][ni][h * 2 + 0] * linv,
                            acc[mi][ni][h * 2 + 1] * linv};
                *reinterpret_cast<float2*>(
                    &out[(size_t)(base + qrow) * DM + col]) = o;
            }
        }
    }
}

// ===========================================================================
extern "C" void kernel_launch(void* const* d_in, const int* in_sizes, int n_in,
                              void* d_out, int out_size)
{
    const float* X  = (const float*)d_in[0];
    const float* Wq = (const float*)d_in[1];
    const float* bq = (const float*)d_in[2];
    const float* Wk = (const float*)d_in[3];
    const float* bk = (const float*)d_in[4];
    const float* Wv = (const float*)d_in[5];
    const float* bv = (const float*)d_in[6];
    float* out = (float*)d_out;

    round_x_kernel<<<(size_t)ROWS * DM / 4 / 256, 256>>>(X);
    transpose_wv_kernel<<<dim3(32, 32), dim3(32, 8)>>>(Wv);
    prep_qk_kernel<<<dim3(32, 4), dim3(32, 8)>>>(Wq, bq, Wk, bk);
    gemm_tc_kernel<<<dim3(128, 9), 256>>>(bv);              // V + Q|K projections
    score_kernel<<<dim3(136, 8), 256>>>();                  // S = QK^T/8 (causal)
    rowexp_kernel<<<ROWS / 8, 256>>>();                     // softmax (in place)
    pv_kernel<<<dim3(S / 128, DM / 128, B), 256>>>(out);    // O = P V / l
}